// round 15
// baseline (speedup 1.0000x reference)
#include <cuda_runtime.h>
#include <cuda_bf16.h>
#include <math.h>

#define L 17
#define DM 128
#define DIN 324
#define DI 256
#define NH 32
#define NL 8
#define CD 320
#define DP 608
#define EPSV 1e-5f
#define NT 320
#define TP 20   // transposed-row pad (floats): 80B, 16B-aligned

// smem layout (float offsets)
#define SX_OFF   0                       // sx:   17*128 = 2176
#define ST_OFF   2176                    // sT:   324*20 = 6480 (rows>=256 tail holds sda)
#define SZX_OFF  (ST_OFF + 6480)         // szx:  17*608 = 10336 (dead z-region = staging)
#define SMEM_FLOATS (SZX_OFF + 10336)    // 18992 floats = 75968 B
#define SDA_OFF  (ST_OFF + 256*TP)       // sda: 17*32 float2 inside sT tail

typedef unsigned long long u64;

__device__ float g_WTin[NL*128*DP];    // [l][k][j]  in_proj_w^T
__device__ float g_WTout[NL*DI*DM];    // [l][k][j]  out_proj_w^T
__device__ float g_WTinp[DIN*64];      // [k][j]     input_w^T
__device__ float g_WToutp[DM*DIN];     // [k][j]     output_w^T

__global__ void k_transpose(const float* __restrict__ inw,
                            const float* __restrict__ outw,
                            const float* __restrict__ inpw,
                            const float* __restrict__ outpw) {
    int idx = blockIdx.x*blockDim.x + threadIdx.x;
    int stride = gridDim.x*blockDim.x;
    for (int i = idx; i < NL*128*DP; i += stride) {
        int l = i/(128*DP), r = i - l*(128*DP), k = r/DP, j = r - k*DP;
        g_WTin[i] = inw[(l*DP + j)*128 + k];
    }
    for (int i = idx; i < NL*DI*DM; i += stride) {
        int l = i/(DI*DM), r = i - l*(DI*DM), k = r/DM, j = r - k*DM;
        g_WTout[i] = outw[(l*DM + j)*DI + k];
    }
    for (int i = idx; i < DIN*64; i += stride) {
        int k = i/64, j = i - k*64;
        g_WTinp[i] = inpw[j*DIN + k];
    }
    for (int i = idx; i < DM*DIN; i += stride) {
        int k = i/DIN, j = i - k*DIN;
        g_WToutp[i] = outpw[j*DM + k];
    }
}

__device__ __forceinline__ u64 pk(float lo, float hi) {
    u64 r; asm("mov.b64 %0,{%1,%2};" : "=l"(r) : "f"(lo), "f"(hi)); return r;
}
__device__ __forceinline__ void upk(u64 v, float& lo, float& hi) {
    asm("mov.b64 {%0,%1},%2;" : "=f"(lo), "=f"(hi) : "l"(v));
}
__device__ __forceinline__ u64 f2fma(u64 a, u64 b, u64 c) {
    u64 d; asm("fma.rn.f32x2 %0,%1,%2,%3;" : "=l"(d) : "l"(a), "l"(b), "l"(c)); return d;
}
__device__ __forceinline__ u64 f2mul(u64 a, u64 b) {
    u64 d; asm("mul.rn.f32x2 %0,%1,%2;" : "=l"(d) : "l"(a), "l"(b)); return d;
}
__device__ __forceinline__ float siluf(float x) { return x / (1.f + expf(-x)); }

// in_proj / out_proj inner body (18 f2fma on 2 output cols)
#define GEMM2_BODY(base, w, A0, A1)                                           \
    {   u64 w0 = pk((w).x, (w).x), w1 = pk((w).y, (w).y);                      \
        const ulonglong2* xr = (const ulonglong2*)(base);                      \
        ulonglong2 p0 = xr[0], p1 = xr[1], p2 = xr[2], p3 = xr[3];             \
        u64 x8 = ((const u64*)(base))[8];                                      \
        A0[0]=f2fma(p0.x,w0,A0[0]); A1[0]=f2fma(p0.x,w1,A1[0]);                \
        A0[1]=f2fma(p0.y,w0,A0[1]); A1[1]=f2fma(p0.y,w1,A1[1]);                \
        A0[2]=f2fma(p1.x,w0,A0[2]); A1[2]=f2fma(p1.x,w1,A1[2]);                \
        A0[3]=f2fma(p1.y,w0,A0[3]); A1[3]=f2fma(p1.y,w1,A1[3]);                \
        A0[4]=f2fma(p2.x,w0,A0[4]); A1[4]=f2fma(p2.x,w1,A1[4]);                \
        A0[5]=f2fma(p2.y,w0,A0[5]); A1[5]=f2fma(p2.y,w1,A1[5]);                \
        A0[6]=f2fma(p3.x,w0,A0[6]); A1[6]=f2fma(p3.x,w1,A1[6]);                \
        A0[7]=f2fma(p3.y,w0,A0[7]); A1[7]=f2fma(p3.y,w1,A1[7]);                \
        A0[8]=f2fma(x8,  w0,A0[8]); A1[8]=f2fma(x8,  w1,A1[8]); }

// unpack one accumulator set (17 t-values) into v[17]
#define UNPACK17(A, v)                                                        \
    {   _Pragma("unroll")                                                      \
        for (int p = 0; p < 8; p++) upk(A[p], v[2*p], v[2*p+1]);               \
        float _hid; upk(A[8], v[16], _hid); (void)_hid; }

__global__ __launch_bounds__(NT, 2)
void k_model(const float* __restrict__ g_init, const float* __restrict__ g_fut,
             const float* __restrict__ g_tf,   const float* __restrict__ g_sv,
             const float* __restrict__ g_inpb, const float* __restrict__ g_emb,
             const float* __restrict__ g_tw,   const float* __restrict__ g_tb,
             const float* __restrict__ g_sw,   const float* __restrict__ g_sb,
             const float* __restrict__ g_convw,const float* __restrict__ g_convb,
             const float* __restrict__ g_dtb,  const float* __restrict__ g_alog,
             const float* __restrict__ g_dskip,const float* __restrict__ g_mnw,
             const float* __restrict__ g_lnw,  const float* __restrict__ g_outb,
             float* __restrict__ g_out)
{
    extern __shared__ float sm[];
    float*  sx   = sm + SX_OFF;    // [17][128] residual stream
    float*  sT   = sm + ST_OFF;    // transposed operand [rows][TP]
    float*  szx  = sm + SZX_OFF;   // [17][608] zxbcdt / conv / y; dead region = staging
    float2* sda  = (float2*)(sm + SDA_OFF);  // [17][32] {dt, a}

    const int b    = blockIdx.x;
    const int tid  = threadIdx.x;
    const int lane = tid & 31, wid = tid >> 5;
    const float tf = g_tf[b];
    const float sv = g_sv[b];

    // zero sT (pads t=17..19 must be benign; zero them once)
    for (int i = tid; i < DIN*TP; i += NT) sT[i] = 0.f;
    __syncthreads();

    // ---------- prologue: sequence -> transposed sT[k][t] ----------
    for (int i = tid; i < L*DIN; i += NT) {
        int t = i / DIN, k = i - t*DIN;
        float v = (t == 0) ? g_init[b*DIN + k] : g_fut[(b*16 + (t-1))*DIN + k];
        sT[k*TP + t] = v;
    }
    __syncthreads();

    // input GEMM: (17x324)@(324x64), 5-way k-split, f32x2 packed t-pairs
    {
        int j = tid & 63, kg = tid >> 6;          // kg in 0..4
        int k0 = kg * 65;
        int len = (kg < 4) ? 65 : 64;             // 4*65 + 64 = 324
        u64 acc2[9];
        #pragma unroll
        for (int p = 0; p < 9; p++) acc2[p] = 0ull;
        for (int kk = 0; kk < len; kk++) {
            int k = k0 + kk;
            float w = g_WTinp[k*64 + j];
            u64 w2 = pk(w, w);
            const float* base = sT + k*TP;
            const ulonglong2* xr = (const ulonglong2*)base;
            ulonglong2 p0 = xr[0], p1 = xr[1], p2 = xr[2], p3 = xr[3];
            u64 x8 = ((const u64*)base)[8];
            acc2[0]=f2fma(p0.x,w2,acc2[0]);
            acc2[1]=f2fma(p0.y,w2,acc2[1]);
            acc2[2]=f2fma(p1.x,w2,acc2[2]);
            acc2[3]=f2fma(p1.y,w2,acc2[3]);
            acc2[4]=f2fma(p2.x,w2,acc2[4]);
            acc2[5]=f2fma(p2.y,w2,acc2[5]);
            acc2[6]=f2fma(p3.x,w2,acc2[6]);
            acc2[7]=f2fma(p3.y,w2,acc2[7]);
            acc2[8]=f2fma(x8, w2,acc2[8]);
        }
        float acc[L];
        #pragma unroll
        for (int p = 0; p < 8; p++) upk(acc2[p], acc[2*p], acc[2*p+1]);
        { float hid; upk(acc2[8], acc[16], hid); (void)hid; }
        if (kg > 0) {
            #pragma unroll
            for (int t = 0; t < L; t++) szx[(kg-1)*(L*64) + t*64 + j] = acc[t];
        }
        __syncthreads();
        if (kg == 0) {
            float bb = g_inpb[j];
            #pragma unroll
            for (int t = 0; t < L; t++) {
                float s = acc[t] + bb
                        + szx[0*(L*64)+t*64+j] + szx[1*(L*64)+t*64+j]
                        + szx[2*(L*64)+t*64+j] + szx[3*(L*64)+t*64+j];
                sx[t*DM + 64 + j] = s;
            }
        } else if (kg == 1) {
            #pragma unroll
            for (int t = 0; t < L; t++) sx[t*DM + j] = g_emb[t*64 + j];
        }
    }
    __syncthreads();

    // te/se pre-scaling: x*te0*se0 + te1 + se1
    for (int i = tid; i < L*DM; i += NT) {
        int d = i & 127;
        float tea = fmaf(tf, g_tw[d],      g_tb[d]);
        float sea = fmaf(sv, g_sw[d],      g_sb[d]);
        float teb = fmaf(tf, g_tw[DM+d],   g_tb[DM+d]);
        float seb = fmaf(sv, g_sw[DM+d],   g_sb[DM+d]);
        sx[i] = sx[i]*tea*sea + teb + seb;
    }
    __syncthreads();

    // ---------- layers ----------
    for (int l = 0; l < NL; l++) {
        const float* Win  = g_WTin  + l*(128*DP);
        const float* Wout = g_WTout + l*(DI*DM);
        const float* lnw  = g_lnw + l*DM;

        // rmsnorm(x, lnw) -> transposed sT[k][t]; t-pair per warp, float2 stores.
        {
            float lnwr[4];
            #pragma unroll
            for (int c = 0; c < 4; c++) lnwr[c] = lnw[lane + 32*c];
            if (wid < 8) {
                int t0 = 2*wid;
                float v0[4], v1[4]; float ss0 = 0.f, ss1 = 0.f;
                #pragma unroll
                for (int c = 0; c < 4; c++) {
                    v0[c] = sx[t0*DM + lane + 32*c];
                    v1[c] = sx[(t0+1)*DM + lane + 32*c];
                    ss0 = fmaf(v0[c], v0[c], ss0);
                    ss1 = fmaf(v1[c], v1[c], ss1);
                }
                #pragma unroll
                for (int o = 16; o > 0; o >>= 1) {
                    ss0 += __shfl_xor_sync(0xffffffffu, ss0, o);
                    ss1 += __shfl_xor_sync(0xffffffffu, ss1, o);
                }
                float sc0 = rsqrtf(ss0*(1.f/128.f) + EPSV);
                float sc1 = rsqrtf(ss1*(1.f/128.f) + EPSV);
                #pragma unroll
                for (int c = 0; c < 4; c++)
                    *(float2*)(sT + (lane + 32*c)*TP + t0) =
                        make_float2(v0[c]*sc0*lnwr[c], v1[c]*sc1*lnwr[c]);
            } else if (wid == 8) {
                const int t = 16;
                float v[4]; float ss = 0.f;
                #pragma unroll
                for (int c = 0; c < 4; c++) {
                    v[c] = sx[t*DM + lane + 32*c];
                    ss = fmaf(v[c], v[c], ss);
                }
                #pragma unroll
                for (int o = 16; o > 0; o >>= 1) ss += __shfl_xor_sync(0xffffffffu, ss, o);
                float sc = rsqrtf(ss*(1.f/128.f) + EPSV);
                #pragma unroll
                for (int c = 0; c < 4; c++)
                    sT[(lane + 32*c)*TP + t] = v[c]*sc*lnwr[c];
            }
        }
        __syncthreads();

        // in_proj: thread handles output cols (2*tid, 2*tid+1), one pass,
        // 4-deep rotating weight prefetch; unroll-8 main loop; FUSED epilogue:
        //   tid <128  -> store raw z
        //   128..287  -> conv + silu in registers, store conv'd xBC/B/C
        //   288..303  -> dt softplus + a, store sda
        if (tid < 304) {
            u64 A0[9], A1[9];
            #pragma unroll
            for (int p = 0; p < 9; p++) { A0[p] = 0ull; A1[p] = 0ull; }
            const float2* Wp = (const float2*)Win + tid;   // stride DP/2 per k
            float2 wbuf[4];
            #pragma unroll
            for (int i = 0; i < 4; i++) wbuf[i] = Wp[i*(DP/2)];
            #pragma unroll 8
            for (int k = 0; k < 120; k++) {
                float2 w = wbuf[k & 3];
                wbuf[k & 3] = Wp[(k+4)*(DP/2)];
                GEMM2_BODY(sT + k*TP, w, A0, A1);
            }
            #pragma unroll
            for (int k = 120; k < 124; k++) {
                float2 w = wbuf[k & 3];
                wbuf[k & 3] = Wp[(k+4)*(DP/2)];
                GEMM2_BODY(sT + k*TP, w, A0, A1);
            }
            #pragma unroll
            for (int k = 124; k < 128; k++) {
                float2 w = wbuf[k & 3];
                GEMM2_BODY(sT + k*TP, w, A0, A1);
            }

            if (tid < 128) {
                // z region: store raw (silu applied later in scan shadow)
                #pragma unroll
                for (int p = 0; p < 8; p++) {
                    float x0,x1,y0,y1;
                    upk(A0[p], x0, x1); upk(A1[p], y0, y1);
                    ((float2*)(szx + (2*p  )*DP))[tid] = make_float2(x0, y0);
                    ((float2*)(szx + (2*p+1)*DP))[tid] = make_float2(x1, y1);
                }
                { float x0,x1,y0,y1;
                  upk(A0[8], x0, x1); upk(A1[8], y0, y1);
                  (void)x1; (void)y1;
                  ((float2*)(szx + 16*DP))[tid] = make_float2(x0, y0); }
            } else if (tid < 288) {
                // conv channels c0 = 2*tid-256, c0+1: conv + silu in registers
                int c0 = 2*tid - 256;
                {
                    float v[L];
                    UNPACK17(A0, v);
                    const float* cw = g_convw + (l*CD + c0)*4;
                    float w0=cw[0], w1=cw[1], w2=cw[2], w3=cw[3];
                    float cb = g_convb[l*CD + c0];
                    #pragma unroll
                    for (int t = 0; t < L; t++) {
                        float s = fmaf(w3, v[t], cb);
                        if (t >= 1) s = fmaf(w2, v[t-1], s);
                        if (t >= 2) s = fmaf(w1, v[t-2], s);
                        if (t >= 3) s = fmaf(w0, v[t-3], s);
                        szx[t*DP + 256 + c0] = siluf(s);
                    }
                }
                {
                    float v[L];
                    UNPACK17(A1, v);
                    const float* cw = g_convw + (l*CD + c0+1)*4;
                    float w0=cw[0], w1=cw[1], w2=cw[2], w3=cw[3];
                    float cb = g_convb[l*CD + c0+1];
                    #pragma unroll
                    for (int t = 0; t < L; t++) {
                        float s = fmaf(w3, v[t], cb);
                        if (t >= 1) s = fmaf(w2, v[t-1], s);
                        if (t >= 2) s = fmaf(w1, v[t-2], s);
                        if (t >= 3) s = fmaf(w0, v[t-3], s);
                        szx[t*DP + 256 + c0+1] = siluf(s);
                    }
                }
            } else {
                // dt heads h0 = 2*(tid-288), h0+1: softplus + a -> sda
                int h0 = 2*(tid - 288);
                {
                    float v[L];
                    UNPACK17(A0, v);
                    float dtb  = g_dtb[l*NH + h0];
                    float aexp = expf(g_alog[l*NH + h0]);
                    #pragma unroll
                    for (int t = 0; t < L; t++) {
                        float raw = v[t] + dtb;
                        float dtv = (raw > 20.f) ? raw : log1pf(expf(raw));
                        sda[t*NH + h0] = make_float2(dtv, expf(-aexp*dtv));
                    }
                }
                {
                    float v[L];
                    UNPACK17(A1, v);
                    float dtb  = g_dtb[l*NH + h0+1];
                    float aexp = expf(g_alog[l*NH + h0+1]);
                    #pragma unroll
                    for (int t = 0; t < L; t++) {
                        float raw = v[t] + dtb;
                        float dtv = (raw > 20.f) ? raw : log1pf(expf(raw));
                        sda[t*NH + h0+1] = make_float2(dtv, expf(-aexp*dtv));
                    }
                }
            }
        }
        __syncthreads();

        // SSM scan on warps 0-7: fully unrolled t-loop, y buffered in regs.
        // Warps 8-9 precompute silu(z) in place (cols 0..255, disjoint).
        if (tid < 256) {
            int h = tid >> 3;
            float Dh = g_dskip[l*NH + h];
            u64 st2[16];
            float yout[L];
            #pragma unroll
            for (int n = 0; n < 16; n++) st2[n] = 0ull;
            #pragma unroll
            for (int t = 0; t < L; t++) {
                float xsv = szx[t*DP + 256 + tid];
                float2 da = sda[t*NH + h];
                float xd  = xsv * da.x;
                u64 xd2 = pk(xd, xd), at2 = pk(da.y, da.y);
                u64 y2a = 0ull, y2b = 0ull;
                const ulonglong2* B2 = (const ulonglong2*)(szx + t*DP + 512);
                const ulonglong2* C2 = (const ulonglong2*)(szx + t*DP + 544);
                #pragma unroll
                for (int n = 0; n < 8; n++) {
                    ulonglong2 bb = B2[n], cc = C2[n];
                    st2[2*n  ] = f2fma(at2, st2[2*n  ], f2mul(xd2, bb.x));
                    y2a = f2fma(st2[2*n  ], cc.x, y2a);
                    st2[2*n+1] = f2fma(at2, st2[2*n+1], f2mul(xd2, bb.y));
                    y2b = f2fma(st2[2*n+1], cc.y, y2b);
                }
                float ya0, ya1, yb0, yb1;
                upk(y2a, ya0, ya1); upk(y2b, yb0, yb1);
                yout[t] = fmaf(xsv, Dh, (ya0 + ya1) + (yb0 + yb1));
            }
            #pragma unroll
            for (int t = 0; t < L; t++)
                szx[t*DP + 256 + tid] = yout[t];
        } else {
            for (int i = tid - 256; i < L*256; i += 64) {
                int t = i >> 8, c = i & 255;
                float z = szx[t*DP + c];
                szx[t*DP + c] = siluf(z);
            }
        }
        __syncthreads();

        // gating y*zs + mixer rmsnorm -> sT[k][t]; t-pair per warp, float2 stores.
        {
            const float* mnw = g_mnw + l*DI;
            float mnwr[8];
            #pragma unroll
            for (int i = 0; i < 8; i++) mnwr[i] = mnw[lane + 32*i];
            if (wid < 8) {
                int t0 = 2*wid;
                float g0[8], g1[8]; float ss0 = 0.f, ss1 = 0.f;
                #pragma unroll
                for (int i = 0; i < 8; i++) {
                    int k = lane + 32*i;
                    float zs0 = szx[t0*DP + k];
                    float y0  = szx[t0*DP + 256 + k];
                    float zs1 = szx[(t0+1)*DP + k];
                    float y1  = szx[(t0+1)*DP + 256 + k];
                    g0[i] = y0 * zs0;
                    g1[i] = y1 * zs1;
                    ss0 = fmaf(g0[i], g0[i], ss0);
                    ss1 = fmaf(g1[i], g1[i], ss1);
                }
                #pragma unroll
                for (int o = 16; o > 0; o >>= 1) {
                    ss0 += __shfl_xor_sync(0xffffffffu, ss0, o);
                    ss1 += __shfl_xor_sync(0xffffffffu, ss1, o);
                }
                float sc0 = rsqrtf(ss0*(1.f/256.f) + EPSV);
                float sc1 = rsqrtf(ss1*(1.f/256.f) + EPSV);
                #pragma unroll
                for (int i = 0; i < 8; i++)
                    *(float2*)(sT + (lane + 32*i)*TP + t0) =
                        make_float2(g0[i]*sc0*mnwr[i], g1[i]*sc1*mnwr[i]);
            } else if (wid == 8) {
                const int t = 16;
                float vg[8]; float ss = 0.f;
                #pragma unroll
                for (int i = 0; i < 8; i++) {
                    int k = lane + 32*i;
                    float zs = szx[t*DP + k];
                    float y  = szx[t*DP + 256 + k];
                    vg[i] = y * zs;
                    ss = fmaf(vg[i], vg[i], ss);
                }
                #pragma unroll
                for (int o = 16; o > 0; o >>= 1) ss += __shfl_xor_sync(0xffffffffu, ss, o);
                float sc = rsqrtf(ss*(1.f/256.f) + EPSV);
                #pragma unroll
                for (int i = 0; i < 8; i++)
                    sT[(lane + 32*i)*TP + t] = vg[i]*sc*mnwr[i];
            }
        }
        __syncthreads();

        // out_proj: 4-way k-split x 2 adjacent cols per thread (256 threads),
        // unroll-8 main loop, de-predicated prefetch; partials staged in dead
        // szx, float2 reduce.
        if (tid < 256) {
            int q  = tid >> 6;     // k-quarter 0..3
            int jp = tid & 63;     // col pair: cols 2jp, 2jp+1
            const float2* wb = (const float2*)(Wout + (q*64)*DM) + jp;
            const float* tb2 = sT + (q*64)*TP;
            u64 A0[9], A1[9];
            #pragma unroll
            for (int p = 0; p < 9; p++) { A0[p] = 0ull; A1[p] = 0ull; }
            float2 wbuf[4];
            #pragma unroll
            for (int i = 0; i < 4; i++) wbuf[i] = wb[i*(DM/2)];
            #pragma unroll 8
            for (int kk = 0; kk < 56; kk++) {
                float2 w = wbuf[kk & 3];
                wbuf[kk & 3] = wb[(kk+4)*(DM/2)];
                GEMM2_BODY(tb2 + kk*TP, w, A0, A1);
            }
            #pragma unroll
            for (int kk = 56; kk < 60; kk++) {
                float2 w = wbuf[kk & 3];
                wbuf[kk & 3] = wb[(kk+4)*(DM/2)];
                GEMM2_BODY(tb2 + kk*TP, w, A0, A1);
            }
            #pragma unroll
            for (int kk = 60; kk < 64; kk++) {
                float2 w = wbuf[kk & 3];
                GEMM2_BODY(tb2 + kk*TP, w, A0, A1);
            }
            float* stg = szx + q*(L*DM);
            #pragma unroll
            for (int p = 0; p < 8; p++) {
                float x0,x1,y0,y1;
                upk(A0[p], x0, x1); upk(A1[p], y0, y1);
                ((float2*)(stg + (2*p  )*DM))[jp] = make_float2(x0, y0);
                ((float2*)(stg + (2*p+1)*DM))[jp] = make_float2(x1, y1);
            }
            { float x0,x1,y0,y1;
              upk(A0[8], x0, x1); upk(A1[8], y0, y1);
              (void)x1; (void)y1;
              ((float2*)(stg + 16*DM))[jp] = make_float2(x0, y0); }
        }
        __syncthreads();
        if (tid < 256) {
            int jp = tid & 63, tq = tid >> 6;
            int t0 = (tq == 0) ? 0 : 1 + tq*4;          // {0,5,9,13}
            int t1 = t0 + ((tq == 0) ? 5 : 4);          // {5,9,13,17}
            for (int t = t0; t < t1; t++) {
                float2 s0 = ((const float2*)(szx + 0*(L*DM) + t*DM))[jp];
                float2 s1 = ((const float2*)(szx + 1*(L*DM) + t*DM))[jp];
                float2 s2 = ((const float2*)(szx + 2*(L*DM) + t*DM))[jp];
                float2 s3 = ((const float2*)(szx + 3*(L*DM) + t*DM))[jp];
                float2* px = (float2*)(sx + t*DM) + jp;
                float2 old = *px;
                *px = make_float2(old.x + s0.x + s1.x + s2.x + s3.x,
                                  old.y + s0.y + s1.y + s2.y + s3.y);
            }
        }
        __syncthreads();
    } // layers

    // ---------- epilogue: final scale + output GEMM over t=1..16 ----------
    {
        float* sE = sT;   // reuse, rows d=0..127, stride TP
        for (int i = tid; i < 16*DM; i += NT) {
            int tt = i >> 7, d = i & 127;
            float te2 = fmaf(tf, g_tw[256+d], g_tb[256+d]);
            float se2 = fmaf(sv, g_sw[256+d], g_sb[256+d]);
            float te3 = fmaf(tf, g_tw[384+d], g_tb[384+d]);
            float se3 = fmaf(sv, g_sw[384+d], g_sb[384+d]);
            sE[d*TP + tt] = sx[(tt+1)*DM + d]*te2*se2 + te3 + se3;
        }
        __syncthreads();

        // 162 threads x 2 adjacent cols, unroll-8 main loop
        if (tid < 162) {
            const float2* wb = (const float2*)g_WToutp + tid;  // stride DIN/2 per k
            u64 A0[8], A1[8];
            #pragma unroll
            for (int p = 0; p < 8; p++) { A0[p] = 0ull; A1[p] = 0ull; }
            float2 wbuf[4];
            #pragma unroll
            for (int i = 0; i < 4; i++) wbuf[i] = wb[i*(DIN/2)];
            #pragma unroll 8
            for (int k = 0; k < 120; k++) {
                float2 w = wbuf[k & 3];
                wbuf[k & 3] = wb[(k+4)*(DIN/2)];
                u64 w0 = pk(w.x, w.x), w1 = pk(w.y, w.y);
                const ulonglong2* xr = (const ulonglong2*)(sE + k*TP);
                ulonglong2 p0 = xr[0], p1 = xr[1], p2 = xr[2], p3 = xr[3];
                A0[0]=f2fma(p0.x,w0,A0[0]); A1[0]=f2fma(p0.x,w1,A1[0]);
                A0[1]=f2fma(p0.y,w0,A0[1]); A1[1]=f2fma(p0.y,w1,A1[1]);
                A0[2]=f2fma(p1.x,w0,A0[2]); A1[2]=f2fma(p1.x,w1,A1[2]);
                A0[3]=f2fma(p1.y,w0,A0[3]); A1[3]=f2fma(p1.y,w1,A1[3]);
                A0[4]=f2fma(p2.x,w0,A0[4]); A1[4]=f2fma(p2.x,w1,A1[4]);
                A0[5]=f2fma(p2.y,w0,A0[5]); A1[5]=f2fma(p2.y,w1,A1[5]);
                A0[6]=f2fma(p3.x,w0,A0[6]); A1[6]=f2fma(p3.x,w1,A1[6]);
                A0[7]=f2fma(p3.y,w0,A0[7]); A1[7]=f2fma(p3.y,w1,A1[7]);
            }
            #pragma unroll
            for (int k = 120; k < 124; k++) {
                float2 w = wbuf[k & 3];
                wbuf[k & 3] = wb[(k+4)*(DIN/2)];
                u64 w0 = pk(w.x, w.x), w1 = pk(w.y, w.y);
                const ulonglong2* xr = (const ulonglong2*)(sE + k*TP);
                ulonglong2 p0 = xr[0], p1 = xr[1], p2 = xr[2], p3 = xr[3];
                A0[0]=f2fma(p0.x,w0,A0[0]); A1[0]=f2fma(p0.x,w1,A1[0]);
                A0[1]=f2fma(p0.y,w0,A0[1]); A1[1]=f2fma(p0.y,w1,A1[1]);
                A0[2]=f2fma(p1.x,w0,A0[2]); A1[2]=f2fma(p1.x,w1,A1[2]);
                A0[3]=f2fma(p1.y,w0,A0[3]); A1[3]=f2fma(p1.y,w1,A1[3]);
                A0[4]=f2fma(p2.x,w0,A0[4]); A1[4]=f2fma(p2.x,w1,A1[4]);
                A0[5]=f2fma(p2.y,w0,A0[5]); A1[5]=f2fma(p2.y,w1,A1[5]);
                A0[6]=f2fma(p3.x,w0,A0[6]); A1[6]=f2fma(p3.x,w1,A1[6]);
                A0[7]=f2fma(p3.y,w0,A0[7]); A1[7]=f2fma(p3.y,w1,A1[7]);
            }
            #pragma unroll
            for (int k = 124; k < 128; k++) {
                float2 w = wbuf[k & 3];
                u64 w0 = pk(w.x, w.x), w1 = pk(w.y, w.y);
                const ulonglong2* xr = (const ulonglong2*)(sE + k*TP);
                ulonglong2 p0 = xr[0], p1 = xr[1], p2 = xr[2], p3 = xr[3];
                A0[0]=f2fma(p0.x,w0,A0[0]); A1[0]=f2fma(p0.x,w1,A1[0]);
                A0[1]=f2fma(p0.y,w0,A0[1]); A1[1]=f2fma(p0.y,w1,A1[1]);
                A0[2]=f2fma(p1.x,w0,A0[2]); A1[2]=f2fma(p1.x,w1,A1[2]);
                A0[3]=f2fma(p1.y,w0,A0[3]); A1[3]=f2fma(p1.y,w1,A1[3]);
                A0[4]=f2fma(p2.x,w0,A0[4]); A1[4]=f2fma(p2.x,w1,A1[4]);
                A0[5]=f2fma(p2.y,w0,A0[5]); A1[5]=f2fma(p2.y,w1,A1[5]);
                A0[6]=f2fma(p3.x,w0,A0[6]); A1[6]=f2fma(p3.x,w1,A1[6]);
                A0[7]=f2fma(p3.y,w0,A0[7]); A1[7]=f2fma(p3.y,w1,A1[7]);
            }
            float ob0 = g_outb[2*tid], ob1 = g_outb[2*tid+1];
            #pragma unroll
            for (int p = 0; p < 8; p++) {
                float x0,x1,y0,y1;
                upk(A0[p], x0, x1); upk(A1[p], y0, y1);
                ((float2*)(g_out + (u64)(b*16 + 2*p  )*DIN))[tid] = make_float2(x0+ob0, y0+ob1);
                ((float2*)(g_out + (u64)(b*16 + 2*p+1)*DIN))[tid] = make_float2(x1+ob0, y1+ob1);
            }
        }
    }
}

extern "C" void kernel_launch(void* const* d_in, const int* in_sizes, int n_in,
                              void* d_out, int out_size) {
    const float* init_states = (const float*)d_in[0];
    const float* future      = (const float*)d_in[1];
    const float* time_flags  = (const float*)d_in[2];
    const float* shortcut    = (const float*)d_in[3];
    const float* input_w     = (const float*)d_in[4];
    const float* input_b     = (const float*)d_in[5];
    const float* states_emb  = (const float*)d_in[6];
    const float* time_w      = (const float*)d_in[7];
    const float* time_b      = (const float*)d_in[8];
    const float* short_w     = (const float*)d_in[9];
    const float* short_b     = (const float*)d_in[10];
    const float* in_proj_w   = (const float*)d_in[11];
    const float* conv_w      = (const float*)d_in[12];
    const float* conv_b      = (const float*)d_in[13];
    const float* dt_bias     = (const float*)d_in[14];
    const float* A_log       = (const float*)d_in[15];
    const float* D_skip      = (const float*)d_in[16];
    const float* mixer_nw    = (const float*)d_in[17];
    const float* out_proj_w  = (const float*)d_in[18];
    const float* layer_nw    = (const float*)d_in[19];
    const float* output_w    = (const float*)d_in[20];
    const float* output_b    = (const float*)d_in[21];
    float* out = (float*)d_out;

    const int smem_bytes = SMEM_FLOATS * 4;   // 75968 B
    cudaFuncSetAttribute(k_model, cudaFuncAttributeMaxDynamicSharedMemorySize, smem_bytes);

    k_transpose<<<512, 256>>>(in_proj_w, out_proj_w, input_w, output_w);
    k_model<<<4096, NT, smem_bytes>>>(init_states, future, time_flags, shortcut,
                                      input_b, states_emb, time_w, time_b,
                                      short_w, short_b, conv_w, conv_b,
                                      dt_bias, A_log, D_skip, mixer_nw,
                                      layer_nw, output_b, out);
}

// round 16
// speedup vs baseline: 1.0075x; 1.0075x over previous
#include <cuda_runtime.h>
#include <cuda_bf16.h>
#include <math.h>

#define L 17
#define DM 128
#define DIN 324
#define DI 256
#define NH 32
#define NL 8
#define CD 320
#define DP 608
#define EPSV 1e-5f
#define NT 320
#define TP 20   // transposed-row pad (floats): 80B, 16B-aligned

// smem layout (float offsets)
#define SX_OFF   0                       // sx:   17*128 = 2176
#define ST_OFF   2176                    // sT:   324*20 = 6480 (rows>=256 tail holds sda)
#define SZX_OFF  (ST_OFF + 6480)         // szx:  17*608 = 10336 (dead z-region = staging)
#define SMEM_FLOATS (SZX_OFF + 10336)    // 18992 floats = 75968 B
#define SDA_OFF  (ST_OFF + 256*TP)       // sda: 17*32 float2 inside sT tail

typedef unsigned long long u64;

__device__ float g_WTin[NL*128*DP];    // [l][k][j]  in_proj_w^T
__device__ float g_WTout[NL*DI*DM];    // [l][k][j]  out_proj_w^T
__device__ float g_WTinp[DIN*64];      // [k][j]     input_w^T
__device__ float g_WToutp[DM*DIN];     // [k][j]     output_w^T

__global__ void k_transpose(const float* __restrict__ inw,
                            const float* __restrict__ outw,
                            const float* __restrict__ inpw,
                            const float* __restrict__ outpw) {
    int idx = blockIdx.x*blockDim.x + threadIdx.x;
    int stride = gridDim.x*blockDim.x;
    for (int i = idx; i < NL*128*DP; i += stride) {
        int l = i/(128*DP), r = i - l*(128*DP), k = r/DP, j = r - k*DP;
        g_WTin[i] = inw[(l*DP + j)*128 + k];
    }
    for (int i = idx; i < NL*DI*DM; i += stride) {
        int l = i/(DI*DM), r = i - l*(DI*DM), k = r/DM, j = r - k*DM;
        g_WTout[i] = outw[(l*DM + j)*DI + k];
    }
    for (int i = idx; i < DIN*64; i += stride) {
        int k = i/64, j = i - k*64;
        g_WTinp[i] = inpw[j*DIN + k];
    }
    for (int i = idx; i < DM*DIN; i += stride) {
        int k = i/DIN, j = i - k*DIN;
        g_WToutp[i] = outpw[j*DM + k];
    }
}

__device__ __forceinline__ u64 pk(float lo, float hi) {
    u64 r; asm("mov.b64 %0,{%1,%2};" : "=l"(r) : "f"(lo), "f"(hi)); return r;
}
__device__ __forceinline__ void upk(u64 v, float& lo, float& hi) {
    asm("mov.b64 {%0,%1},%2;" : "=f"(lo), "=f"(hi) : "l"(v));
}
__device__ __forceinline__ u64 f2fma(u64 a, u64 b, u64 c) {
    u64 d; asm("fma.rn.f32x2 %0,%1,%2,%3;" : "=l"(d) : "l"(a), "l"(b), "l"(c)); return d;
}
__device__ __forceinline__ u64 f2mul(u64 a, u64 b) {
    u64 d; asm("mul.rn.f32x2 %0,%1,%2;" : "=l"(d) : "l"(a), "l"(b)); return d;
}
__device__ __forceinline__ float siluf(float x) { return x / (1.f + expf(-x)); }

// in_proj / out_proj inner body (18 f2fma on 2 output cols)
#define GEMM2_BODY(base, w, A0, A1)                                           \
    {   u64 w0 = pk((w).x, (w).x), w1 = pk((w).y, (w).y);                      \
        const ulonglong2* xr = (const ulonglong2*)(base);                      \
        ulonglong2 p0 = xr[0], p1 = xr[1], p2 = xr[2], p3 = xr[3];             \
        u64 x8 = ((const u64*)(base))[8];                                      \
        A0[0]=f2fma(p0.x,w0,A0[0]); A1[0]=f2fma(p0.x,w1,A1[0]);                \
        A0[1]=f2fma(p0.y,w0,A0[1]); A1[1]=f2fma(p0.y,w1,A1[1]);                \
        A0[2]=f2fma(p1.x,w0,A0[2]); A1[2]=f2fma(p1.x,w1,A1[2]);                \
        A0[3]=f2fma(p1.y,w0,A0[3]); A1[3]=f2fma(p1.y,w1,A1[3]);                \
        A0[4]=f2fma(p2.x,w0,A0[4]); A1[4]=f2fma(p2.x,w1,A1[4]);                \
        A0[5]=f2fma(p2.y,w0,A0[5]); A1[5]=f2fma(p2.y,w1,A1[5]);                \
        A0[6]=f2fma(p3.x,w0,A0[6]); A1[6]=f2fma(p3.x,w1,A1[6]);                \
        A0[7]=f2fma(p3.y,w0,A0[7]); A1[7]=f2fma(p3.y,w1,A1[7]);                \
        A0[8]=f2fma(x8,  w0,A0[8]); A1[8]=f2fma(x8,  w1,A1[8]); }

__global__ __launch_bounds__(NT, 2)
void k_model(const float* __restrict__ g_init, const float* __restrict__ g_fut,
             const float* __restrict__ g_tf,   const float* __restrict__ g_sv,
             const float* __restrict__ g_inpb, const float* __restrict__ g_emb,
             const float* __restrict__ g_tw,   const float* __restrict__ g_tb,
             const float* __restrict__ g_sw,   const float* __restrict__ g_sb,
             const float* __restrict__ g_convw,const float* __restrict__ g_convb,
             const float* __restrict__ g_dtb,  const float* __restrict__ g_alog,
             const float* __restrict__ g_dskip,const float* __restrict__ g_mnw,
             const float* __restrict__ g_lnw,  const float* __restrict__ g_outb,
             float* __restrict__ g_out)
{
    extern __shared__ float sm[];
    float*  sx   = sm + SX_OFF;    // [17][128] residual stream
    float*  sT   = sm + ST_OFF;    // transposed operand [rows][TP]
    float*  szx  = sm + SZX_OFF;   // [17][608] zxbcdt / conv / y; dead region = staging
    float2* sda  = (float2*)(sm + SDA_OFF);  // [17][32] {dt, a}

    const int b    = blockIdx.x;
    const int tid  = threadIdx.x;
    const int lane = tid & 31, wid = tid >> 5;
    const float tf = g_tf[b];
    const float sv = g_sv[b];

    // zero sT (pads t=17..19 must be benign; zero them once)
    for (int i = tid; i < DIN*TP; i += NT) sT[i] = 0.f;
    __syncthreads();

    // ---------- prologue: sequence -> transposed sT[k][t] ----------
    for (int i = tid; i < L*DIN; i += NT) {
        int t = i / DIN, k = i - t*DIN;
        float v = (t == 0) ? g_init[b*DIN + k] : g_fut[(b*16 + (t-1))*DIN + k];
        sT[k*TP + t] = v;
    }
    __syncthreads();

    // input GEMM: (17x324)@(324x64), 5-way k-split, f32x2 packed t-pairs
    {
        int j = tid & 63, kg = tid >> 6;          // kg in 0..4
        int k0 = kg * 65;
        int len = (kg < 4) ? 65 : 64;             // 4*65 + 64 = 324
        u64 acc2[9];
        #pragma unroll
        for (int p = 0; p < 9; p++) acc2[p] = 0ull;
        for (int kk = 0; kk < len; kk++) {
            int k = k0 + kk;
            float w = g_WTinp[k*64 + j];
            u64 w2 = pk(w, w);
            const float* base = sT + k*TP;
            const ulonglong2* xr = (const ulonglong2*)base;
            ulonglong2 p0 = xr[0], p1 = xr[1], p2 = xr[2], p3 = xr[3];
            u64 x8 = ((const u64*)base)[8];
            acc2[0]=f2fma(p0.x,w2,acc2[0]);
            acc2[1]=f2fma(p0.y,w2,acc2[1]);
            acc2[2]=f2fma(p1.x,w2,acc2[2]);
            acc2[3]=f2fma(p1.y,w2,acc2[3]);
            acc2[4]=f2fma(p2.x,w2,acc2[4]);
            acc2[5]=f2fma(p2.y,w2,acc2[5]);
            acc2[6]=f2fma(p3.x,w2,acc2[6]);
            acc2[7]=f2fma(p3.y,w2,acc2[7]);
            acc2[8]=f2fma(x8, w2,acc2[8]);
        }
        float acc[L];
        #pragma unroll
        for (int p = 0; p < 8; p++) upk(acc2[p], acc[2*p], acc[2*p+1]);
        { float hid; upk(acc2[8], acc[16], hid); (void)hid; }
        if (kg > 0) {
            #pragma unroll
            for (int t = 0; t < L; t++) szx[(kg-1)*(L*64) + t*64 + j] = acc[t];
        }
        __syncthreads();
        if (kg == 0) {
            float bb = g_inpb[j];
            #pragma unroll
            for (int t = 0; t < L; t++) {
                float s = acc[t] + bb
                        + szx[0*(L*64)+t*64+j] + szx[1*(L*64)+t*64+j]
                        + szx[2*(L*64)+t*64+j] + szx[3*(L*64)+t*64+j];
                sx[t*DM + 64 + j] = s;
            }
        } else if (kg == 1) {
            #pragma unroll
            for (int t = 0; t < L; t++) sx[t*DM + j] = g_emb[t*64 + j];
        }
    }
    __syncthreads();

    // te/se pre-scaling: x*te0*se0 + te1 + se1
    for (int i = tid; i < L*DM; i += NT) {
        int d = i & 127;
        float tea = fmaf(tf, g_tw[d],      g_tb[d]);
        float sea = fmaf(sv, g_sw[d],      g_sb[d]);
        float teb = fmaf(tf, g_tw[DM+d],   g_tb[DM+d]);
        float seb = fmaf(sv, g_sw[DM+d],   g_sb[DM+d]);
        sx[i] = sx[i]*tea*sea + teb + seb;
    }
    __syncthreads();

    // ---------- layers ----------
    for (int l = 0; l < NL; l++) {
        const float* Win  = g_WTin  + l*(128*DP);
        const float* Wout = g_WTout + l*(DI*DM);
        const float* lnw  = g_lnw + l*DM;

        // rmsnorm(x, lnw) -> transposed sT[k][t]; t-pair per warp, float2 stores.
        {
            float lnwr[4];
            #pragma unroll
            for (int c = 0; c < 4; c++) lnwr[c] = lnw[lane + 32*c];
            if (wid < 8) {
                int t0 = 2*wid;
                float v0[4], v1[4]; float ss0 = 0.f, ss1 = 0.f;
                #pragma unroll
                for (int c = 0; c < 4; c++) {
                    v0[c] = sx[t0*DM + lane + 32*c];
                    v1[c] = sx[(t0+1)*DM + lane + 32*c];
                    ss0 = fmaf(v0[c], v0[c], ss0);
                    ss1 = fmaf(v1[c], v1[c], ss1);
                }
                #pragma unroll
                for (int o = 16; o > 0; o >>= 1) {
                    ss0 += __shfl_xor_sync(0xffffffffu, ss0, o);
                    ss1 += __shfl_xor_sync(0xffffffffu, ss1, o);
                }
                float sc0 = rsqrtf(ss0*(1.f/128.f) + EPSV);
                float sc1 = rsqrtf(ss1*(1.f/128.f) + EPSV);
                #pragma unroll
                for (int c = 0; c < 4; c++)
                    *(float2*)(sT + (lane + 32*c)*TP + t0) =
                        make_float2(v0[c]*sc0*lnwr[c], v1[c]*sc1*lnwr[c]);
            } else if (wid == 8) {
                const int t = 16;
                float v[4]; float ss = 0.f;
                #pragma unroll
                for (int c = 0; c < 4; c++) {
                    v[c] = sx[t*DM + lane + 32*c];
                    ss = fmaf(v[c], v[c], ss);
                }
                #pragma unroll
                for (int o = 16; o > 0; o >>= 1) ss += __shfl_xor_sync(0xffffffffu, ss, o);
                float sc = rsqrtf(ss*(1.f/128.f) + EPSV);
                #pragma unroll
                for (int c = 0; c < 4; c++)
                    sT[(lane + 32*c)*TP + t] = v[c]*sc*lnwr[c];
            }
        }
        __syncthreads();

        // in_proj: thread handles output cols (2*tid, 2*tid+1), one pass,
        // 4-deep rotating weight prefetch; unroll-8 main loop, de-predicated tail.
        if (tid < 304) {
            u64 A0[9], A1[9];
            #pragma unroll
            for (int p = 0; p < 9; p++) { A0[p] = 0ull; A1[p] = 0ull; }
            const float2* Wp = (const float2*)Win + tid;   // stride DP/2 per k
            float2 wbuf[4];
            #pragma unroll
            for (int i = 0; i < 4; i++) wbuf[i] = Wp[i*(DP/2)];
            #pragma unroll 8
            for (int k = 0; k < 120; k++) {
                float2 w = wbuf[k & 3];
                wbuf[k & 3] = Wp[(k+4)*(DP/2)];
                GEMM2_BODY(sT + k*TP, w, A0, A1);
            }
            #pragma unroll
            for (int k = 120; k < 124; k++) {
                float2 w = wbuf[k & 3];
                wbuf[k & 3] = Wp[(k+4)*(DP/2)];
                GEMM2_BODY(sT + k*TP, w, A0, A1);
            }
            #pragma unroll
            for (int k = 124; k < 128; k++) {
                float2 w = wbuf[k & 3];
                GEMM2_BODY(sT + k*TP, w, A0, A1);
            }
            #pragma unroll
            for (int p = 0; p < 8; p++) {
                float x0,x1,y0,y1;
                upk(A0[p], x0, x1); upk(A1[p], y0, y1);
                ((float2*)(szx + (2*p  )*DP))[tid] = make_float2(x0, y0);
                ((float2*)(szx + (2*p+1)*DP))[tid] = make_float2(x1, y1);
            }
            { float x0,x1,y0,y1;
              upk(A0[8], x0, x1); upk(A1[8], y0, y1);
              (void)x1; (void)y1;
              ((float2*)(szx + 16*DP))[tid] = make_float2(x0, y0); }
        }
        __syncthreads();

        // dt & a -> interleaved sda[t][h] = {dt, a} (reads raw cols 576..607)
        for (int i = tid; i < L*NH; i += NT) {
            int t = i >> 5, h = i & 31;
            float raw = szx[t*DP + 576 + h] + g_dtb[l*NH + h];
            float dtv = (raw > 20.f) ? raw : log1pf(expf(raw));
            float av  = expf(-expf(g_alog[l*NH + h]) * dtv);
            sda[i] = make_float2(dtv, av);
        }
        // causal depthwise conv + silu, in place on cols 256..575 (channel = tid)
        {
            int c = tid;
            const float* cw = g_convw + (l*CD + c)*4;
            float w0 = cw[0], w1 = cw[1], w2 = cw[2], w3 = cw[3];
            float cb = g_convb[l*CD + c];
            float v[L];
            #pragma unroll
            for (int t = 0; t < L; t++) v[t] = szx[t*DP + 256 + c];
            #pragma unroll
            for (int t = 0; t < L; t++) {
                float s = fmaf(w3, v[t], cb);
                if (t >= 1) s = fmaf(w2, v[t-1], s);
                if (t >= 2) s = fmaf(w1, v[t-2], s);
                if (t >= 3) s = fmaf(w0, v[t-3], s);
                szx[t*DP + 256 + c] = siluf(s);
            }
        }
        __syncthreads();

        // SSM scan on warps 0-7: fully unrolled t-loop, y buffered in regs.
        // Warps 8-9 precompute silu(z) in place with float2 (cols 0..255).
        if (tid < 256) {
            int h = tid >> 3;
            float Dh = g_dskip[l*NH + h];
            u64 st2[16];
            float yout[L];
            #pragma unroll
            for (int n = 0; n < 16; n++) st2[n] = 0ull;
            #pragma unroll
            for (int t = 0; t < L; t++) {
                float xsv = szx[t*DP + 256 + tid];
                float2 da = sda[t*NH + h];
                float xd  = xsv * da.x;
                u64 xd2 = pk(xd, xd), at2 = pk(da.y, da.y);
                u64 y2a = 0ull, y2b = 0ull;
                const ulonglong2* B2 = (const ulonglong2*)(szx + t*DP + 512);
                const ulonglong2* C2 = (const ulonglong2*)(szx + t*DP + 544);
                #pragma unroll
                for (int n = 0; n < 8; n++) {
                    ulonglong2 bb = B2[n], cc = C2[n];
                    st2[2*n  ] = f2fma(at2, st2[2*n  ], f2mul(xd2, bb.x));
                    y2a = f2fma(st2[2*n  ], cc.x, y2a);
                    st2[2*n+1] = f2fma(at2, st2[2*n+1], f2mul(xd2, bb.y));
                    y2b = f2fma(st2[2*n+1], cc.y, y2b);
                }
                float ya0, ya1, yb0, yb1;
                upk(y2a, ya0, ya1); upk(y2b, yb0, yb1);
                yout[t] = fmaf(xsv, Dh, (ya0 + ya1) + (yb0 + yb1));
            }
            #pragma unroll
            for (int t = 0; t < L; t++)
                szx[t*DP + 256 + tid] = yout[t];
        } else {
            for (int i = tid - 256; i < L*128; i += 64) {   // 128 float2 per t
                int t = i >> 7, c = i & 127;
                float2* p = (float2*)(szx + t*DP) + c;
                float2 z = *p;
                *p = make_float2(siluf(z.x), siluf(z.y));
            }
        }
        __syncthreads();

        // gating y*zs + mixer rmsnorm -> sT[k][t]; float2 loads (k=2*lane+64i),
        // t-pair per warp, float2 transposed stores.
        {
            const float2* mnw2 = (const float2*)(g_mnw + l*DI);
            float2 mnwr[4];
            #pragma unroll
            for (int i = 0; i < 4; i++) mnwr[i] = mnw2[lane + 32*i];
            if (wid < 8) {
                int t0 = 2*wid;
                float g0[8], g1[8]; float ss0 = 0.f, ss1 = 0.f;
                #pragma unroll
                for (int i = 0; i < 4; i++) {
                    int kf = lane + 32*i;   // float2 index -> cols 2kf, 2kf+1
                    float2 zs0 = ((const float2*)(szx + t0*DP))[kf];
                    float2 yv0 = ((const float2*)(szx + t0*DP + 256))[kf];
                    float2 zs1 = ((const float2*)(szx + (t0+1)*DP))[kf];
                    float2 yv1 = ((const float2*)(szx + (t0+1)*DP + 256))[kf];
                    g0[2*i  ] = yv0.x * zs0.x;
                    g0[2*i+1] = yv0.y * zs0.y;
                    g1[2*i  ] = yv1.x * zs1.x;
                    g1[2*i+1] = yv1.y * zs1.y;
                    ss0 = fmaf(g0[2*i], g0[2*i], fmaf(g0[2*i+1], g0[2*i+1], ss0));
                    ss1 = fmaf(g1[2*i], g1[2*i], fmaf(g1[2*i+1], g1[2*i+1], ss1));
                }
                #pragma unroll
                for (int o = 16; o > 0; o >>= 1) {
                    ss0 += __shfl_xor_sync(0xffffffffu, ss0, o);
                    ss1 += __shfl_xor_sync(0xffffffffu, ss1, o);
                }
                float sc0 = rsqrtf(ss0*(1.f/256.f) + EPSV);
                float sc1 = rsqrtf(ss1*(1.f/256.f) + EPSV);
                #pragma unroll
                for (int i = 0; i < 4; i++) {
                    int k = 2*(lane + 32*i);
                    *(float2*)(sT + k*TP + t0) =
                        make_float2(g0[2*i]*sc0*mnwr[i].x, g1[2*i]*sc1*mnwr[i].x);
                    *(float2*)(sT + (k+1)*TP + t0) =
                        make_float2(g0[2*i+1]*sc0*mnwr[i].y, g1[2*i+1]*sc1*mnwr[i].y);
                }
            } else if (wid == 8) {
                const int t = 16;
                float vg[8]; float ss = 0.f;
                #pragma unroll
                for (int i = 0; i < 4; i++) {
                    int kf = lane + 32*i;
                    float2 zs = ((const float2*)(szx + t*DP))[kf];
                    float2 yv = ((const float2*)(szx + t*DP + 256))[kf];
                    vg[2*i  ] = yv.x * zs.x;
                    vg[2*i+1] = yv.y * zs.y;
                    ss = fmaf(vg[2*i], vg[2*i], fmaf(vg[2*i+1], vg[2*i+1], ss));
                }
                #pragma unroll
                for (int o = 16; o > 0; o >>= 1) ss += __shfl_xor_sync(0xffffffffu, ss, o);
                float sc = rsqrtf(ss*(1.f/256.f) + EPSV);
                #pragma unroll
                for (int i = 0; i < 4; i++) {
                    int k = 2*(lane + 32*i);
                    sT[k*TP + t]     = vg[2*i]*sc*mnwr[i].x;
                    sT[(k+1)*TP + t] = vg[2*i+1]*sc*mnwr[i].y;
                }
            }
        }
        __syncthreads();

        // out_proj: 4-way k-split x 2 adjacent cols per thread (256 threads),
        // unroll-8 main loop, de-predicated prefetch; partials staged in dead
        // szx, float4 reduce.
        if (tid < 256) {
            int q  = tid >> 6;     // k-quarter 0..3
            int jp = tid & 63;     // col pair: cols 2jp, 2jp+1
            const float2* wb = (const float2*)(Wout + (q*64)*DM) + jp;
            const float* tb2 = sT + (q*64)*TP;
            u64 A0[9], A1[9];
            #pragma unroll
            for (int p = 0; p < 9; p++) { A0[p] = 0ull; A1[p] = 0ull; }
            float2 wbuf[4];
            #pragma unroll
            for (int i = 0; i < 4; i++) wbuf[i] = wb[i*(DM/2)];
            #pragma unroll 8
            for (int kk = 0; kk < 56; kk++) {
                float2 w = wbuf[kk & 3];
                wbuf[kk & 3] = wb[(kk+4)*(DM/2)];
                GEMM2_BODY(tb2 + kk*TP, w, A0, A1);
            }
            #pragma unroll
            for (int kk = 56; kk < 60; kk++) {
                float2 w = wbuf[kk & 3];
                wbuf[kk & 3] = wb[(kk+4)*(DM/2)];
                GEMM2_BODY(tb2 + kk*TP, w, A0, A1);
            }
            #pragma unroll
            for (int kk = 60; kk < 64; kk++) {
                float2 w = wbuf[kk & 3];
                GEMM2_BODY(tb2 + kk*TP, w, A0, A1);
            }
            float* stg = szx + q*(L*DM);
            #pragma unroll
            for (int p = 0; p < 8; p++) {
                float x0,x1,y0,y1;
                upk(A0[p], x0, x1); upk(A1[p], y0, y1);
                ((float2*)(stg + (2*p  )*DM))[jp] = make_float2(x0, y0);
                ((float2*)(stg + (2*p+1)*DM))[jp] = make_float2(x1, y1);
            }
            { float x0,x1,y0,y1;
              upk(A0[8], x0, x1); upk(A1[8], y0, y1);
              (void)x1; (void)y1;
              ((float2*)(stg + 16*DM))[jp] = make_float2(x0, y0); }
        }
        __syncthreads();
        // reduce: 256 threads = 32 col-quads x 8 t-groups, float4 ops
        if (tid < 256) {
            int jq = tid & 31, tg = tid >> 5;
            int t0 = (tg == 0) ? 0 : 3 + (tg-1)*2;      // {0,3,5,7,9,11,13,15}
            int t1 = (tg == 0) ? 3 : t0 + 2;            // group0: 3 t, rest: 2 t
            for (int t = t0; t < t1; t++) {
                float4 s0 = ((const float4*)(szx + 0*(L*DM) + t*DM))[jq];
                float4 s1 = ((const float4*)(szx + 1*(L*DM) + t*DM))[jq];
                float4 s2 = ((const float4*)(szx + 2*(L*DM) + t*DM))[jq];
                float4 s3 = ((const float4*)(szx + 3*(L*DM) + t*DM))[jq];
                float4* px = (float4*)(sx + t*DM) + jq;
                float4 old = *px;
                *px = make_float4(old.x + s0.x + s1.x + s2.x + s3.x,
                                  old.y + s0.y + s1.y + s2.y + s3.y,
                                  old.z + s0.z + s1.z + s2.z + s3.z,
                                  old.w + s0.w + s1.w + s2.w + s3.w);
            }
        }
        __syncthreads();
    } // layers

    // ---------- epilogue: final scale + output GEMM over t=1..16 ----------
    {
        float* sE = sT;   // reuse, rows d=0..127, stride TP
        for (int i = tid; i < 16*DM; i += NT) {
            int tt = i >> 7, d = i & 127;
            float te2 = fmaf(tf, g_tw[256+d], g_tb[256+d]);
            float se2 = fmaf(sv, g_sw[256+d], g_sb[256+d]);
            float te3 = fmaf(tf, g_tw[384+d], g_tb[384+d]);
            float se3 = fmaf(sv, g_sw[384+d], g_sb[384+d]);
            sE[d*TP + tt] = sx[(tt+1)*DM + d]*te2*se2 + te3 + se3;
        }
        __syncthreads();

        // 162 threads x 2 adjacent cols, unroll-8 main loop
        if (tid < 162) {
            const float2* wb = (const float2*)g_WToutp + tid;  // stride DIN/2 per k
            u64 A0[8], A1[8];
            #pragma unroll
            for (int p = 0; p < 8; p++) { A0[p] = 0ull; A1[p] = 0ull; }
            float2 wbuf[4];
            #pragma unroll
            for (int i = 0; i < 4; i++) wbuf[i] = wb[i*(DIN/2)];
            #pragma unroll 8
            for (int k = 0; k < 120; k++) {
                float2 w = wbuf[k & 3];
                wbuf[k & 3] = wb[(k+4)*(DIN/2)];
                u64 w0 = pk(w.x, w.x), w1 = pk(w.y, w.y);
                const ulonglong2* xr = (const ulonglong2*)(sE + k*TP);
                ulonglong2 p0 = xr[0], p1 = xr[1], p2 = xr[2], p3 = xr[3];
                A0[0]=f2fma(p0.x,w0,A0[0]); A1[0]=f2fma(p0.x,w1,A1[0]);
                A0[1]=f2fma(p0.y,w0,A0[1]); A1[1]=f2fma(p0.y,w1,A1[1]);
                A0[2]=f2fma(p1.x,w0,A0[2]); A1[2]=f2fma(p1.x,w1,A1[2]);
                A0[3]=f2fma(p1.y,w0,A0[3]); A1[3]=f2fma(p1.y,w1,A1[3]);
                A0[4]=f2fma(p2.x,w0,A0[4]); A1[4]=f2fma(p2.x,w1,A1[4]);
                A0[5]=f2fma(p2.y,w0,A0[5]); A1[5]=f2fma(p2.y,w1,A1[5]);
                A0[6]=f2fma(p3.x,w0,A0[6]); A1[6]=f2fma(p3.x,w1,A1[6]);
                A0[7]=f2fma(p3.y,w0,A0[7]); A1[7]=f2fma(p3.y,w1,A1[7]);
            }
            #pragma unroll
            for (int k = 120; k < 124; k++) {
                float2 w = wbuf[k & 3];
                wbuf[k & 3] = wb[(k+4)*(DIN/2)];
                u64 w0 = pk(w.x, w.x), w1 = pk(w.y, w.y);
                const ulonglong2* xr = (const ulonglong2*)(sE + k*TP);
                ulonglong2 p0 = xr[0], p1 = xr[1], p2 = xr[2], p3 = xr[3];
                A0[0]=f2fma(p0.x,w0,A0[0]); A1[0]=f2fma(p0.x,w1,A1[0]);
                A0[1]=f2fma(p0.y,w0,A0[1]); A1[1]=f2fma(p0.y,w1,A1[1]);
                A0[2]=f2fma(p1.x,w0,A0[2]); A1[2]=f2fma(p1.x,w1,A1[2]);
                A0[3]=f2fma(p1.y,w0,A0[3]); A1[3]=f2fma(p1.y,w1,A1[3]);
                A0[4]=f2fma(p2.x,w0,A0[4]); A1[4]=f2fma(p2.x,w1,A1[4]);
                A0[5]=f2fma(p2.y,w0,A0[5]); A1[5]=f2fma(p2.y,w1,A1[5]);
                A0[6]=f2fma(p3.x,w0,A0[6]); A1[6]=f2fma(p3.x,w1,A1[6]);
                A0[7]=f2fma(p3.y,w0,A0[7]); A1[7]=f2fma(p3.y,w1,A1[7]);
            }
            #pragma unroll
            for (int k = 124; k < 128; k++) {
                float2 w = wbuf[k & 3];
                u64 w0 = pk(w.x, w.x), w1 = pk(w.y, w.y);
                const ulonglong2* xr = (const ulonglong2*)(sE + k*TP);
                ulonglong2 p0 = xr[0], p1 = xr[1], p2 = xr[2], p3 = xr[3];
                A0[0]=f2fma(p0.x,w0,A0[0]); A1[0]=f2fma(p0.x,w1,A1[0]);
                A0[1]=f2fma(p0.y,w0,A0[1]); A1[1]=f2fma(p0.y,w1,A1[1]);
                A0[2]=f2fma(p1.x,w0,A0[2]); A1[2]=f2fma(p1.x,w1,A1[2]);
                A0[3]=f2fma(p1.y,w0,A0[3]); A1[3]=f2fma(p1.y,w1,A1[3]);
                A0[4]=f2fma(p2.x,w0,A0[4]); A1[4]=f2fma(p2.x,w1,A1[4]);
                A0[5]=f2fma(p2.y,w0,A0[5]); A1[5]=f2fma(p2.y,w1,A1[5]);
                A0[6]=f2fma(p3.x,w0,A0[6]); A1[6]=f2fma(p3.x,w1,A1[6]);
                A0[7]=f2fma(p3.y,w0,A0[7]); A1[7]=f2fma(p3.y,w1,A1[7]);
            }
            float ob0 = g_outb[2*tid], ob1 = g_outb[2*tid+1];
            #pragma unroll
            for (int p = 0; p < 8; p++) {
                float x0,x1,y0,y1;
                upk(A0[p], x0, x1); upk(A1[p], y0, y1);
                ((float2*)(g_out + (u64)(b*16 + 2*p  )*DIN))[tid] = make_float2(x0+ob0, y0+ob1);
                ((float2*)(g_out + (u64)(b*16 + 2*p+1)*DIN))[tid] = make_float2(x1+ob0, y1+ob1);
            }
        }
    }
}

extern "C" void kernel_launch(void* const* d_in, const int* in_sizes, int n_in,
                              void* d_out, int out_size) {
    const float* init_states = (const float*)d_in[0];
    const float* future      = (const float*)d_in[1];
    const float* time_flags  = (const float*)d_in[2];
    const float* shortcut    = (const float*)d_in[3];
    const float* input_w     = (const float*)d_in[4];
    const float* input_b     = (const float*)d_in[5];
    const float* states_emb  = (const float*)d_in[6];
    const float* time_w      = (const float*)d_in[7];
    const float* time_b      = (const float*)d_in[8];
    const float* short_w     = (const float*)d_in[9];
    const float* short_b     = (const float*)d_in[10];
    const float* in_proj_w   = (const float*)d_in[11];
    const float* conv_w      = (const float*)d_in[12];
    const float* conv_b      = (const float*)d_in[13];
    const float* dt_bias     = (const float*)d_in[14];
    const float* A_log       = (const float*)d_in[15];
    const float* D_skip      = (const float*)d_in[16];
    const float* mixer_nw    = (const float*)d_in[17];
    const float* out_proj_w  = (const float*)d_in[18];
    const float* layer_nw    = (const float*)d_in[19];
    const float* output_w    = (const float*)d_in[20];
    const float* output_b    = (const float*)d_in[21];
    float* out = (float*)d_out;

    const int smem_bytes = SMEM_FLOATS * 4;   // 75968 B
    cudaFuncSetAttribute(k_model, cudaFuncAttributeMaxDynamicSharedMemorySize, smem_bytes);

    k_transpose<<<512, 256>>>(in_proj_w, out_proj_w, input_w, output_w);
    k_model<<<4096, NT, smem_bytes>>>(init_states, future, time_flags, shortcut,
                                      input_b, states_emb, time_w, time_b,
                                      short_w, short_b, conv_w, conv_b,
                                      dt_bias, A_log, D_skip, mixer_nw,
                                      layer_nw, output_b, out);
}

// round 17
// speedup vs baseline: 1.0261x; 1.0186x over previous
#include <cuda_runtime.h>
#include <cuda_bf16.h>
#include <math.h>

#define L 17
#define DM 128
#define DIN 324
#define DI 256
#define NH 32
#define NL 8
#define CD 320
#define DP 608
#define EPSV 1e-5f
#define NT 320
#define TP 20   // transposed-row pad (floats): 80B, 16B-aligned

// smem layout (float offsets)
#define SX_OFF   0                       // sx:   17*128 = 2176
#define ST_OFF   2176                    // sT:   324*20 = 6480 (rows>=256 tail holds sda)
#define SZX_OFF  (ST_OFF + 6480)         // szx:  17*608 = 10336 (dead z-region = staging)
#define SMEM_FLOATS (SZX_OFF + 10336)    // 18992 floats = 75968 B
#define SDA_OFF  (ST_OFF + 256*TP)       // sda: 17*32 float2 inside sT tail

typedef unsigned long long u64;

__device__ float g_WTin[NL*128*DP];    // [l][k][j]  in_proj_w^T
__device__ float g_WTout[NL*DI*DM];    // [l][k][j]  out_proj_w^T
__device__ float g_WTinp[DIN*64];      // [k][j]     input_w^T
__device__ float g_WToutp[DM*DIN];     // [k][j]     output_w^T

__global__ void k_transpose(const float* __restrict__ inw,
                            const float* __restrict__ outw,
                            const float* __restrict__ inpw,
                            const float* __restrict__ outpw) {
    int idx = blockIdx.x*blockDim.x + threadIdx.x;
    int stride = gridDim.x*blockDim.x;
    for (int i = idx; i < NL*128*DP; i += stride) {
        int l = i/(128*DP), r = i - l*(128*DP), k = r/DP, j = r - k*DP;
        g_WTin[i] = inw[(l*DP + j)*128 + k];
    }
    for (int i = idx; i < NL*DI*DM; i += stride) {
        int l = i/(DI*DM), r = i - l*(DI*DM), k = r/DM, j = r - k*DM;
        g_WTout[i] = outw[(l*DM + j)*DI + k];
    }
    for (int i = idx; i < DIN*64; i += stride) {
        int k = i/64, j = i - k*64;
        g_WTinp[i] = inpw[j*DIN + k];
    }
    for (int i = idx; i < DM*DIN; i += stride) {
        int k = i/DIN, j = i - k*DIN;
        g_WToutp[i] = outpw[j*DM + k];
    }
}

__device__ __forceinline__ u64 pk(float lo, float hi) {
    u64 r; asm("mov.b64 %0,{%1,%2};" : "=l"(r) : "f"(lo), "f"(hi)); return r;
}
__device__ __forceinline__ void upk(u64 v, float& lo, float& hi) {
    asm("mov.b64 {%0,%1},%2;" : "=f"(lo), "=f"(hi) : "l"(v));
}
__device__ __forceinline__ u64 f2fma(u64 a, u64 b, u64 c) {
    u64 d; asm("fma.rn.f32x2 %0,%1,%2,%3;" : "=l"(d) : "l"(a), "l"(b), "l"(c)); return d;
}
__device__ __forceinline__ u64 f2mul(u64 a, u64 b) {
    u64 d; asm("mul.rn.f32x2 %0,%1,%2;" : "=l"(d) : "l"(a), "l"(b)); return d;
}
__device__ __forceinline__ float siluf(float x) { return x / (1.f + expf(-x)); }

// in_proj / out_proj inner body (18 f2fma on 2 output cols)
#define GEMM2_BODY(base, w, A0, A1)                                           \
    {   u64 w0 = pk((w).x, (w).x), w1 = pk((w).y, (w).y);                      \
        const ulonglong2* xr = (const ulonglong2*)(base);                      \
        ulonglong2 p0 = xr[0], p1 = xr[1], p2 = xr[2], p3 = xr[3];             \
        u64 x8 = ((const u64*)(base))[8];                                      \
        A0[0]=f2fma(p0.x,w0,A0[0]); A1[0]=f2fma(p0.x,w1,A1[0]);                \
        A0[1]=f2fma(p0.y,w0,A0[1]); A1[1]=f2fma(p0.y,w1,A1[1]);                \
        A0[2]=f2fma(p1.x,w0,A0[2]); A1[2]=f2fma(p1.x,w1,A1[2]);                \
        A0[3]=f2fma(p1.y,w0,A0[3]); A1[3]=f2fma(p1.y,w1,A1[3]);                \
        A0[4]=f2fma(p2.x,w0,A0[4]); A1[4]=f2fma(p2.x,w1,A1[4]);                \
        A0[5]=f2fma(p2.y,w0,A0[5]); A1[5]=f2fma(p2.y,w1,A1[5]);                \
        A0[6]=f2fma(p3.x,w0,A0[6]); A1[6]=f2fma(p3.x,w1,A1[6]);                \
        A0[7]=f2fma(p3.y,w0,A0[7]); A1[7]=f2fma(p3.y,w1,A1[7]);                \
        A0[8]=f2fma(x8,  w0,A0[8]); A1[8]=f2fma(x8,  w1,A1[8]); }

__global__ __launch_bounds__(NT, 2)
void k_model(const float* __restrict__ g_init, const float* __restrict__ g_fut,
             const float* __restrict__ g_tf,   const float* __restrict__ g_sv,
             const float* __restrict__ g_inpb, const float* __restrict__ g_emb,
             const float* __restrict__ g_tw,   const float* __restrict__ g_tb,
             const float* __restrict__ g_sw,   const float* __restrict__ g_sb,
             const float* __restrict__ g_convw,const float* __restrict__ g_convb,
             const float* __restrict__ g_dtb,  const float* __restrict__ g_alog,
             const float* __restrict__ g_dskip,const float* __restrict__ g_mnw,
             const float* __restrict__ g_lnw,  const float* __restrict__ g_outb,
             float* __restrict__ g_out)
{
    extern __shared__ float sm[];
    float*  sx   = sm + SX_OFF;    // [17][128] residual stream
    float*  sT   = sm + ST_OFF;    // transposed operand [rows][TP]
    float*  szx  = sm + SZX_OFF;   // [17][608] zxbcdt / conv / y; dead region = staging
    float2* sda  = (float2*)(sm + SDA_OFF);  // [17][32] {dt, a}

    const int b    = blockIdx.x;
    const int tid  = threadIdx.x;
    const int lane = tid & 31, wid = tid >> 5;
    const float tf = g_tf[b];
    const float sv = g_sv[b];

    // zero sT (pads t=17..19 must be benign; zero them once)
    for (int i = tid; i < DIN*TP; i += NT) sT[i] = 0.f;
    __syncthreads();

    // ---------- prologue: sequence -> transposed sT[k][t] ----------
    for (int i = tid; i < L*DIN; i += NT) {
        int t = i / DIN, k = i - t*DIN;
        float v = (t == 0) ? g_init[b*DIN + k] : g_fut[(b*16 + (t-1))*DIN + k];
        sT[k*TP + t] = v;
    }
    __syncthreads();

    // input GEMM: (17x324)@(324x64), 5-way k-split, f32x2 packed t-pairs
    {
        int j = tid & 63, kg = tid >> 6;          // kg in 0..4
        int k0 = kg * 65;
        int len = (kg < 4) ? 65 : 64;             // 4*65 + 64 = 324
        u64 acc2[9];
        #pragma unroll
        for (int p = 0; p < 9; p++) acc2[p] = 0ull;
        for (int kk = 0; kk < len; kk++) {
            int k = k0 + kk;
            float w = g_WTinp[k*64 + j];
            u64 w2 = pk(w, w);
            const float* base = sT + k*TP;
            const ulonglong2* xr = (const ulonglong2*)base;
            ulonglong2 p0 = xr[0], p1 = xr[1], p2 = xr[2], p3 = xr[3];
            u64 x8 = ((const u64*)base)[8];
            acc2[0]=f2fma(p0.x,w2,acc2[0]);
            acc2[1]=f2fma(p0.y,w2,acc2[1]);
            acc2[2]=f2fma(p1.x,w2,acc2[2]);
            acc2[3]=f2fma(p1.y,w2,acc2[3]);
            acc2[4]=f2fma(p2.x,w2,acc2[4]);
            acc2[5]=f2fma(p2.y,w2,acc2[5]);
            acc2[6]=f2fma(p3.x,w2,acc2[6]);
            acc2[7]=f2fma(p3.y,w2,acc2[7]);
            acc2[8]=f2fma(x8, w2,acc2[8]);
        }
        float acc[L];
        #pragma unroll
        for (int p = 0; p < 8; p++) upk(acc2[p], acc[2*p], acc[2*p+1]);
        { float hid; upk(acc2[8], acc[16], hid); (void)hid; }
        if (kg > 0) {
            #pragma unroll
            for (int t = 0; t < L; t++) szx[(kg-1)*(L*64) + t*64 + j] = acc[t];
        }
        __syncthreads();
        if (kg == 0) {
            float bb = g_inpb[j];
            #pragma unroll
            for (int t = 0; t < L; t++) {
                float s = acc[t] + bb
                        + szx[0*(L*64)+t*64+j] + szx[1*(L*64)+t*64+j]
                        + szx[2*(L*64)+t*64+j] + szx[3*(L*64)+t*64+j];
                sx[t*DM + 64 + j] = s;
            }
        } else if (kg == 1) {
            #pragma unroll
            for (int t = 0; t < L; t++) sx[t*DM + j] = g_emb[t*64 + j];
        }
    }
    __syncthreads();

    // te/se pre-scaling: x*te0*se0 + te1 + se1
    for (int i = tid; i < L*DM; i += NT) {
        int d = i & 127;
        float tea = fmaf(tf, g_tw[d],      g_tb[d]);
        float sea = fmaf(sv, g_sw[d],      g_sb[d]);
        float teb = fmaf(tf, g_tw[DM+d],   g_tb[DM+d]);
        float seb = fmaf(sv, g_sw[DM+d],   g_sb[DM+d]);
        sx[i] = sx[i]*tea*sea + teb + seb;
    }
    __syncthreads();

    // ---------- layers ----------
    for (int l = 0; l < NL; l++) {
        const float* Win  = g_WTin  + l*(128*DP);
        const float* Wout = g_WTout + l*(DI*DM);
        const float* lnw  = g_lnw + l*DM;

        // rmsnorm(x, lnw) -> transposed sT[k][t]; t-pair per warp, float2 stores.
        {
            float lnwr[4];
            #pragma unroll
            for (int c = 0; c < 4; c++) lnwr[c] = lnw[lane + 32*c];
            if (wid < 8) {
                int t0 = 2*wid;
                float v0[4], v1[4]; float ss0 = 0.f, ss1 = 0.f;
                #pragma unroll
                for (int c = 0; c < 4; c++) {
                    v0[c] = sx[t0*DM + lane + 32*c];
                    v1[c] = sx[(t0+1)*DM + lane + 32*c];
                    ss0 = fmaf(v0[c], v0[c], ss0);
                    ss1 = fmaf(v1[c], v1[c], ss1);
                }
                #pragma unroll
                for (int o = 16; o > 0; o >>= 1) {
                    ss0 += __shfl_xor_sync(0xffffffffu, ss0, o);
                    ss1 += __shfl_xor_sync(0xffffffffu, ss1, o);
                }
                float sc0 = rsqrtf(ss0*(1.f/128.f) + EPSV);
                float sc1 = rsqrtf(ss1*(1.f/128.f) + EPSV);
                #pragma unroll
                for (int c = 0; c < 4; c++)
                    *(float2*)(sT + (lane + 32*c)*TP + t0) =
                        make_float2(v0[c]*sc0*lnwr[c], v1[c]*sc1*lnwr[c]);
            } else if (wid == 8) {
                const int t = 16;
                float v[4]; float ss = 0.f;
                #pragma unroll
                for (int c = 0; c < 4; c++) {
                    v[c] = sx[t*DM + lane + 32*c];
                    ss = fmaf(v[c], v[c], ss);
                }
                #pragma unroll
                for (int o = 16; o > 0; o >>= 1) ss += __shfl_xor_sync(0xffffffffu, ss, o);
                float sc = rsqrtf(ss*(1.f/128.f) + EPSV);
                #pragma unroll
                for (int c = 0; c < 4; c++)
                    sT[(lane + 32*c)*TP + t] = v[c]*sc*lnwr[c];
            }
        }
        __syncthreads();

        // in_proj: thread handles output cols (2*tid, 2*tid+1), one pass,
        // 4-deep rotating weight prefetch; unroll-8 main loop, de-predicated tail.
        if (tid < 304) {
            u64 A0[9], A1[9];
            #pragma unroll
            for (int p = 0; p < 9; p++) { A0[p] = 0ull; A1[p] = 0ull; }
            const float2* Wp = (const float2*)Win + tid;   // stride DP/2 per k
            float2 wbuf[4];
            #pragma unroll
            for (int i = 0; i < 4; i++) wbuf[i] = Wp[i*(DP/2)];
            #pragma unroll 8
            for (int k = 0; k < 120; k++) {
                float2 w = wbuf[k & 3];
                wbuf[k & 3] = Wp[(k+4)*(DP/2)];
                GEMM2_BODY(sT + k*TP, w, A0, A1);
            }
            #pragma unroll
            for (int k = 120; k < 124; k++) {
                float2 w = wbuf[k & 3];
                wbuf[k & 3] = Wp[(k+4)*(DP/2)];
                GEMM2_BODY(sT + k*TP, w, A0, A1);
            }
            #pragma unroll
            for (int k = 124; k < 128; k++) {
                float2 w = wbuf[k & 3];
                GEMM2_BODY(sT + k*TP, w, A0, A1);
            }
            #pragma unroll
            for (int p = 0; p < 8; p++) {
                float x0,x1,y0,y1;
                upk(A0[p], x0, x1); upk(A1[p], y0, y1);
                ((float2*)(szx + (2*p  )*DP))[tid] = make_float2(x0, y0);
                ((float2*)(szx + (2*p+1)*DP))[tid] = make_float2(x1, y1);
            }
            { float x0,x1,y0,y1;
              upk(A0[8], x0, x1); upk(A1[8], y0, y1);
              (void)x1; (void)y1;
              ((float2*)(szx + 16*DP))[tid] = make_float2(x0, y0); }
        }
        __syncthreads();

        // dt & a -> interleaved sda[t][h] = {dt, a} (reads raw cols 576..607)
        for (int i = tid; i < L*NH; i += NT) {
            int t = i >> 5, h = i & 31;
            float raw = szx[t*DP + 576 + h] + g_dtb[l*NH + h];
            float dtv = (raw > 20.f) ? raw : log1pf(expf(raw));
            float av  = expf(-expf(g_alog[l*NH + h]) * dtv);
            sda[i] = make_float2(dtv, av);
        }
        // causal depthwise conv + silu, in place on cols 256..575 (channel = tid)
        {
            int c = tid;
            const float* cw = g_convw + (l*CD + c)*4;
            float w0 = cw[0], w1 = cw[1], w2 = cw[2], w3 = cw[3];
            float cb = g_convb[l*CD + c];
            float v[L];
            #pragma unroll
            for (int t = 0; t < L; t++) v[t] = szx[t*DP + 256 + c];
            #pragma unroll
            for (int t = 0; t < L; t++) {
                float s = fmaf(w3, v[t], cb);
                if (t >= 1) s = fmaf(w2, v[t-1], s);
                if (t >= 2) s = fmaf(w1, v[t-2], s);
                if (t >= 3) s = fmaf(w0, v[t-3], s);
                szx[t*DP + 256 + c] = siluf(s);
            }
        }
        __syncthreads();

        // SSM scan on warps 0-7: fully unrolled t-loop, y buffered in regs.
        // Warps 8-9 precompute silu(z) in place with float2 (cols 0..255).
        if (tid < 256) {
            int h = tid >> 3;
            float Dh = g_dskip[l*NH + h];
            u64 st2[16];
            float yout[L];
            #pragma unroll
            for (int n = 0; n < 16; n++) st2[n] = 0ull;
            #pragma unroll
            for (int t = 0; t < L; t++) {
                float xsv = szx[t*DP + 256 + tid];
                float2 da = sda[t*NH + h];
                float xd  = xsv * da.x;
                u64 xd2 = pk(xd, xd), at2 = pk(da.y, da.y);
                u64 y2a = 0ull, y2b = 0ull;
                const ulonglong2* B2 = (const ulonglong2*)(szx + t*DP + 512);
                const ulonglong2* C2 = (const ulonglong2*)(szx + t*DP + 544);
                #pragma unroll
                for (int n = 0; n < 8; n++) {
                    ulonglong2 bb = B2[n], cc = C2[n];
                    st2[2*n  ] = f2fma(at2, st2[2*n  ], f2mul(xd2, bb.x));
                    y2a = f2fma(st2[2*n  ], cc.x, y2a);
                    st2[2*n+1] = f2fma(at2, st2[2*n+1], f2mul(xd2, bb.y));
                    y2b = f2fma(st2[2*n+1], cc.y, y2b);
                }
                float ya0, ya1, yb0, yb1;
                upk(y2a, ya0, ya1); upk(y2b, yb0, yb1);
                yout[t] = fmaf(xsv, Dh, (ya0 + ya1) + (yb0 + yb1));
            }
            #pragma unroll
            for (int t = 0; t < L; t++)
                szx[t*DP + 256 + tid] = yout[t];
        } else {
            for (int i = tid - 256; i < L*128; i += 64) {   // 128 float2 per t
                int t = i >> 7, c = i & 127;
                float2* p = (float2*)(szx + t*DP) + c;
                float2 z = *p;
                *p = make_float2(siluf(z.x), siluf(z.y));
            }
        }
        __syncthreads();

        // gating y*zs + mixer rmsnorm -> sT[k][t]; t-pair per warp, float2 stores.
        {
            const float* mnw = g_mnw + l*DI;
            float mnwr[8];
            #pragma unroll
            for (int i = 0; i < 8; i++) mnwr[i] = mnw[lane + 32*i];
            if (wid < 8) {
                int t0 = 2*wid;
                float g0[8], g1[8]; float ss0 = 0.f, ss1 = 0.f;
                #pragma unroll
                for (int i = 0; i < 8; i++) {
                    int k = lane + 32*i;
                    float zs0 = szx[t0*DP + k];
                    float y0  = szx[t0*DP + 256 + k];
                    float zs1 = szx[(t0+1)*DP + k];
                    float y1  = szx[(t0+1)*DP + 256 + k];
                    g0[i] = y0 * zs0;
                    g1[i] = y1 * zs1;
                    ss0 = fmaf(g0[i], g0[i], ss0);
                    ss1 = fmaf(g1[i], g1[i], ss1);
                }
                #pragma unroll
                for (int o = 16; o > 0; o >>= 1) {
                    ss0 += __shfl_xor_sync(0xffffffffu, ss0, o);
                    ss1 += __shfl_xor_sync(0xffffffffu, ss1, o);
                }
                float sc0 = rsqrtf(ss0*(1.f/256.f) + EPSV);
                float sc1 = rsqrtf(ss1*(1.f/256.f) + EPSV);
                #pragma unroll
                for (int i = 0; i < 8; i++)
                    *(float2*)(sT + (lane + 32*i)*TP + t0) =
                        make_float2(g0[i]*sc0*mnwr[i], g1[i]*sc1*mnwr[i]);
            } else if (wid == 8) {
                const int t = 16;
                float vg[8]; float ss = 0.f;
                #pragma unroll
                for (int i = 0; i < 8; i++) {
                    int k = lane + 32*i;
                    float zs = szx[t*DP + k];
                    float y  = szx[t*DP + 256 + k];
                    vg[i] = y * zs;
                    ss = fmaf(vg[i], vg[i], ss);
                }
                #pragma unroll
                for (int o = 16; o > 0; o >>= 1) ss += __shfl_xor_sync(0xffffffffu, ss, o);
                float sc = rsqrtf(ss*(1.f/256.f) + EPSV);
                #pragma unroll
                for (int i = 0; i < 8; i++)
                    sT[(lane + 32*i)*TP + t] = vg[i]*sc*mnwr[i];
            }
        }
        __syncthreads();

        // out_proj: 4-way k-split x 2 adjacent cols per thread (256 threads),
        // unroll-8 main loop, de-predicated prefetch; partials staged in dead
        // szx, float4 reduce.
        if (tid < 256) {
            int q  = tid >> 6;     // k-quarter 0..3
            int jp = tid & 63;     // col pair: cols 2jp, 2jp+1
            const float2* wb = (const float2*)(Wout + (q*64)*DM) + jp;
            const float* tb2 = sT + (q*64)*TP;
            u64 A0[9], A1[9];
            #pragma unroll
            for (int p = 0; p < 9; p++) { A0[p] = 0ull; A1[p] = 0ull; }
            float2 wbuf[4];
            #pragma unroll
            for (int i = 0; i < 4; i++) wbuf[i] = wb[i*(DM/2)];
            #pragma unroll 8
            for (int kk = 0; kk < 56; kk++) {
                float2 w = wbuf[kk & 3];
                wbuf[kk & 3] = wb[(kk+4)*(DM/2)];
                GEMM2_BODY(tb2 + kk*TP, w, A0, A1);
            }
            #pragma unroll
            for (int kk = 56; kk < 60; kk++) {
                float2 w = wbuf[kk & 3];
                wbuf[kk & 3] = wb[(kk+4)*(DM/2)];
                GEMM2_BODY(tb2 + kk*TP, w, A0, A1);
            }
            #pragma unroll
            for (int kk = 60; kk < 64; kk++) {
                float2 w = wbuf[kk & 3];
                GEMM2_BODY(tb2 + kk*TP, w, A0, A1);
            }
            float* stg = szx + q*(L*DM);
            #pragma unroll
            for (int p = 0; p < 8; p++) {
                float x0,x1,y0,y1;
                upk(A0[p], x0, x1); upk(A1[p], y0, y1);
                ((float2*)(stg + (2*p  )*DM))[jp] = make_float2(x0, y0);
                ((float2*)(stg + (2*p+1)*DM))[jp] = make_float2(x1, y1);
            }
            { float x0,x1,y0,y1;
              upk(A0[8], x0, x1); upk(A1[8], y0, y1);
              (void)x1; (void)y1;
              ((float2*)(stg + 16*DM))[jp] = make_float2(x0, y0); }
        }
        __syncthreads();
        // reduce: 256 threads = 32 col-quads x 8 t-groups, float4 ops
        if (tid < 256) {
            int jq = tid & 31, tg = tid >> 5;
            int t0 = (tg == 0) ? 0 : 3 + (tg-1)*2;      // {0,3,5,7,9,11,13,15}
            int t1 = (tg == 0) ? 3 : t0 + 2;            // group0: 3 t, rest: 2 t
            for (int t = t0; t < t1; t++) {
                float4 s0 = ((const float4*)(szx + 0*(L*DM) + t*DM))[jq];
                float4 s1 = ((const float4*)(szx + 1*(L*DM) + t*DM))[jq];
                float4 s2 = ((const float4*)(szx + 2*(L*DM) + t*DM))[jq];
                float4 s3 = ((const float4*)(szx + 3*(L*DM) + t*DM))[jq];
                float4* px = (float4*)(sx + t*DM) + jq;
                float4 old = *px;
                *px = make_float4(old.x + s0.x + s1.x + s2.x + s3.x,
                                  old.y + s0.y + s1.y + s2.y + s3.y,
                                  old.z + s0.z + s1.z + s2.z + s3.z,
                                  old.w + s0.w + s1.w + s2.w + s3.w);
            }
        }
        __syncthreads();
    } // layers

    // ---------- epilogue: final scale + output GEMM over t=1..16 ----------
    {
        float* sE = sT;   // reuse, rows d=0..127, stride TP
        for (int i = tid; i < 16*DM; i += NT) {
            int tt = i >> 7, d = i & 127;
            float te2 = fmaf(tf, g_tw[256+d], g_tb[256+d]);
            float se2 = fmaf(sv, g_sw[256+d], g_sb[256+d]);
            float te3 = fmaf(tf, g_tw[384+d], g_tb[384+d]);
            float se3 = fmaf(sv, g_sw[384+d], g_sb[384+d]);
            sE[d*TP + tt] = sx[(tt+1)*DM + d]*te2*se2 + te3 + se3;
        }
        __syncthreads();

        // 162 threads x 2 adjacent cols, unroll-8 main loop
        if (tid < 162) {
            const float2* wb = (const float2*)g_WToutp + tid;  // stride DIN/2 per k
            u64 A0[8], A1[8];
            #pragma unroll
            for (int p = 0; p < 8; p++) { A0[p] = 0ull; A1[p] = 0ull; }
            float2 wbuf[4];
            #pragma unroll
            for (int i = 0; i < 4; i++) wbuf[i] = wb[i*(DIN/2)];
            #pragma unroll 8
            for (int k = 0; k < 120; k++) {
                float2 w = wbuf[k & 3];
                wbuf[k & 3] = wb[(k+4)*(DIN/2)];
                u64 w0 = pk(w.x, w.x), w1 = pk(w.y, w.y);
                const ulonglong2* xr = (const ulonglong2*)(sE + k*TP);
                ulonglong2 p0 = xr[0], p1 = xr[1], p2 = xr[2], p3 = xr[3];
                A0[0]=f2fma(p0.x,w0,A0[0]); A1[0]=f2fma(p0.x,w1,A1[0]);
                A0[1]=f2fma(p0.y,w0,A0[1]); A1[1]=f2fma(p0.y,w1,A1[1]);
                A0[2]=f2fma(p1.x,w0,A0[2]); A1[2]=f2fma(p1.x,w1,A1[2]);
                A0[3]=f2fma(p1.y,w0,A0[3]); A1[3]=f2fma(p1.y,w1,A1[3]);
                A0[4]=f2fma(p2.x,w0,A0[4]); A1[4]=f2fma(p2.x,w1,A1[4]);
                A0[5]=f2fma(p2.y,w0,A0[5]); A1[5]=f2fma(p2.y,w1,A1[5]);
                A0[6]=f2fma(p3.x,w0,A0[6]); A1[6]=f2fma(p3.x,w1,A1[6]);
                A0[7]=f2fma(p3.y,w0,A0[7]); A1[7]=f2fma(p3.y,w1,A1[7]);
            }
            #pragma unroll
            for (int k = 120; k < 124; k++) {
                float2 w = wbuf[k & 3];
                wbuf[k & 3] = wb[(k+4)*(DIN/2)];
                u64 w0 = pk(w.x, w.x), w1 = pk(w.y, w.y);
                const ulonglong2* xr = (const ulonglong2*)(sE + k*TP);
                ulonglong2 p0 = xr[0], p1 = xr[1], p2 = xr[2], p3 = xr[3];
                A0[0]=f2fma(p0.x,w0,A0[0]); A1[0]=f2fma(p0.x,w1,A1[0]);
                A0[1]=f2fma(p0.y,w0,A0[1]); A1[1]=f2fma(p0.y,w1,A1[1]);
                A0[2]=f2fma(p1.x,w0,A0[2]); A1[2]=f2fma(p1.x,w1,A1[2]);
                A0[3]=f2fma(p1.y,w0,A0[3]); A1[3]=f2fma(p1.y,w1,A1[3]);
                A0[4]=f2fma(p2.x,w0,A0[4]); A1[4]=f2fma(p2.x,w1,A1[4]);
                A0[5]=f2fma(p2.y,w0,A0[5]); A1[5]=f2fma(p2.y,w1,A1[5]);
                A0[6]=f2fma(p3.x,w0,A0[6]); A1[6]=f2fma(p3.x,w1,A1[6]);
                A0[7]=f2fma(p3.y,w0,A0[7]); A1[7]=f2fma(p3.y,w1,A1[7]);
            }
            #pragma unroll
            for (int k = 124; k < 128; k++) {
                float2 w = wbuf[k & 3];
                u64 w0 = pk(w.x, w.x), w1 = pk(w.y, w.y);
                const ulonglong2* xr = (const ulonglong2*)(sE + k*TP);
                ulonglong2 p0 = xr[0], p1 = xr[1], p2 = xr[2], p3 = xr[3];
                A0[0]=f2fma(p0.x,w0,A0[0]); A1[0]=f2fma(p0.x,w1,A1[0]);
                A0[1]=f2fma(p0.y,w0,A0[1]); A1[1]=f2fma(p0.y,w1,A1[1]);
                A0[2]=f2fma(p1.x,w0,A0[2]); A1[2]=f2fma(p1.x,w1,A1[2]);
                A0[3]=f2fma(p1.y,w0,A0[3]); A1[3]=f2fma(p1.y,w1,A1[3]);
                A0[4]=f2fma(p2.x,w0,A0[4]); A1[4]=f2fma(p2.x,w1,A1[4]);
                A0[5]=f2fma(p2.y,w0,A0[5]); A1[5]=f2fma(p2.y,w1,A1[5]);
                A0[6]=f2fma(p3.x,w0,A0[6]); A1[6]=f2fma(p3.x,w1,A1[6]);
                A0[7]=f2fma(p3.y,w0,A0[7]); A1[7]=f2fma(p3.y,w1,A1[7]);
            }
            float ob0 = g_outb[2*tid], ob1 = g_outb[2*tid+1];
            #pragma unroll
            for (int p = 0; p < 8; p++) {
                float x0,x1,y0,y1;
                upk(A0[p], x0, x1); upk(A1[p], y0, y1);
                ((float2*)(g_out + (u64)(b*16 + 2*p  )*DIN))[tid] = make_float2(x0+ob0, y0+ob1);
                ((float2*)(g_out + (u64)(b*16 + 2*p+1)*DIN))[tid] = make_float2(x1+ob0, y1+ob1);
            }
        }
    }
}

extern "C" void kernel_launch(void* const* d_in, const int* in_sizes, int n_in,
                              void* d_out, int out_size) {
    const float* init_states = (const float*)d_in[0];
    const float* future      = (const float*)d_in[1];
    const float* time_flags  = (const float*)d_in[2];
    const float* shortcut    = (const float*)d_in[3];
    const float* input_w     = (const float*)d_in[4];
    const float* input_b     = (const float*)d_in[5];
    const float* states_emb  = (const float*)d_in[6];
    const float* time_w      = (const float*)d_in[7];
    const float* time_b      = (const float*)d_in[8];
    const float* short_w     = (const float*)d_in[9];
    const float* short_b     = (const float*)d_in[10];
    const float* in_proj_w   = (const float*)d_in[11];
    const float* conv_w      = (const float*)d_in[12];
    const float* conv_b      = (const float*)d_in[13];
    const float* dt_bias     = (const float*)d_in[14];
    const float* A_log       = (const float*)d_in[15];
    const float* D_skip      = (const float*)d_in[16];
    const float* mixer_nw    = (const float*)d_in[17];
    const float* out_proj_w  = (const float*)d_in[18];
    const float* layer_nw    = (const float*)d_in[19];
    const float* output_w    = (const float*)d_in[20];
    const float* output_b    = (const float*)d_in[21];
    float* out = (float*)d_out;

    const int smem_bytes = SMEM_FLOATS * 4;   // 75968 B
    cudaFuncSetAttribute(k_model, cudaFuncAttributeMaxDynamicSharedMemorySize, smem_bytes);

    k_transpose<<<512, 256>>>(in_proj_w, out_proj_w, input_w, output_w);
    k_model<<<4096, NT, smem_bytes>>>(init_states, future, time_flags, shortcut,
                                      input_b, states_emb, time_w, time_b,
                                      short_w, short_b, conv_w, conv_b,
                                      dt_bias, A_log, D_skip, mixer_nw,
                                      layer_nw, output_b, out);
}